// round 1
// baseline (speedup 1.0000x reference)
#include <cuda_runtime.h>

#define BS    8
#define CIN   128
#define NSTK  32
#define NPNT  128
#define CU    256      // 2*CIN: channels entering each GCN
#define COUT  256
#define NDN   4096     // NSTK*NPNT
#define KDN   10
#define ISQ   0.9999950000374997f   // 1/sqrt(1+1e-5)
#define NEG_INF (-1e30f)

// ---------------- scratch (device globals; no runtime allocation) ----------
__device__ float g_sp_in[BS*CU*NSTK];
__device__ float g_xT[(size_t)BS*NDN*CU];          // [b][n][c] point features, row-major
__device__ float g_xx[BS*NDN];                     // squared norms
__device__ float g_dist[(size_t)BS*NDN*NDN];       // neg_dist (536 MB)
__device__ int   g_idx[BS*NDN*KDN];
__device__ float g_ynb[(size_t)BS*NDN*COUT];       // W1 @ x
__device__ float g_yct[(size_t)BS*NDN*COUT];       // (W2-W1) @ x + b
__device__ float g_udn[(size_t)BS*NDN*COUT];       // GCN output, [b][n][o]

// ---------------- 1) sparse input: concat(sparse, max_p dense) -------------
__global__ void k_build_sp_in(const float* __restrict__ sp, const float* __restrict__ dn){
    int e = blockIdx.x*blockDim.x + threadIdx.x;   // 65536 threads
    int b = e >> 13; int r = e & 8191; int c = r >> 5; int s = r & 31;
    float v;
    if (c < CIN) {
        v = sp[(b*CIN + c)*NSTK + s];
    } else {
        const float* p = dn + (((size_t)(b*CIN + (c-CIN))*NSTK + s)*NPNT);
        v = NEG_INF;
        #pragma unroll 8
        for (int i = 0; i < NPNT; i++) v = fmaxf(v, p[i]);
    }
    g_sp_in[e] = v;
}

// ---------------- 2) sparse GCN (N=32, k=2), writes u_sp to d_out ----------
__global__ void k_sparse_gcn(const float* __restrict__ W, const float* __restrict__ bias,
                             const float* __restrict__ gam, const float* __restrict__ bet,
                             float* __restrict__ out){
    int b = blockIdx.x; int oc = blockIdx.y; int tid = threadIdx.x;
    __shared__ float xs[CU*NSTK];       // [c][s]
    __shared__ float xx[NSTK];
    __shared__ float nd[NSTK*NSTK];
    __shared__ int   i1s[NSTK], i2s[NSTK];

    for (int e = tid; e < CU*NSTK; e += 256) xs[e] = g_sp_in[b*CU*NSTK + e];
    __syncthreads();
    if (tid < NSTK){
        float s = 0.f;
        for (int c = 0; c < CU; c++){ float v = xs[c*NSTK+tid]; s += v*v; }
        xx[tid] = s;
    }
    __syncthreads();
    for (int e = tid; e < NSTK*NSTK; e += 256){
        int n = e >> 5, m = e & 31;
        float d = 0.f;
        for (int c = 0; c < CU; c++) d += xs[c*NSTK+n]*xs[c*NSTK+m];
        nd[e] = 2.f*d - xx[n] - xx[m];
    }
    __syncthreads();
    if (tid < NSTK){
        float b1 = NEG_INF, b2 = NEG_INF; int j1 = 0, j2 = 0;
        for (int m = 0; m < NSTK; m++){
            float v = nd[tid*NSTK+m];
            if (v > b1){ b2=b1; j2=j1; b1=v; j1=m; }
            else if (v > b2){ b2=v; j2=m; }
        }
        i1s[tid]=j1; i2s[tid]=j2;
    }
    __syncthreads();

    // h[n,k,o] = W1.x[idx_k] + (W2-W1).x[n] + b ; BN affine ; relu ; max_k
    int o   = oc*32 + (tid >> 3);
    int nb0 = tid & 7;
    float a1[4]={0,0,0,0}, a2[4]={0,0,0,0}, ac[4]={0,0,0,0};
    int j1[4], j2[4];
    #pragma unroll
    for (int u=0;u<4;u++){ int n = nb0 + u*8; j1[u]=i1s[n]; j2[u]=i2s[n]; }
    const float* wr = W + o*(2*CU);
    for (int c = 0; c < CU; c++){
        float w1 = wr[c];
        float wd = wr[CU + c] - w1;
        const float* xc = xs + c*NSTK;
        #pragma unroll
        for (int u=0;u<4;u++){
            int n = nb0 + u*8;
            a1[u] += w1*xc[j1[u]];
            a2[u] += w1*xc[j2[u]];
            ac[u] += wd*xc[n];
        }
    }
    float bo = bias[o], go = gam[o]*ISQ, beo = bet[o];
    #pragma unroll
    for (int u=0;u<4;u++){
        int n = nb0 + u*8;
        float h1 = go*(a1[u]+ac[u]+bo) + beo; h1 = fmaxf(h1, 0.f);
        float h2 = go*(a2[u]+ac[u]+bo) + beo; h2 = fmaxf(h2, 0.f);
        out[(b*COUT + o)*NSTK + n] = fmaxf(h1, h2);
    }
}

// ---------------- 3) dense point features, transposed [b][n][c] ------------
__global__ void k_build_xT(const float* __restrict__ sp, const float* __restrict__ dn){
    int s = blockIdx.x, b = blockIdx.y, tid = threadIdx.x;
    __shared__ float sm[128*65];
    __shared__ float sps[CIN];
    size_t rowbase = (size_t)b*NDN + (size_t)s*NPNT;
    for (int cc0 = 0; cc0 < CIN; cc0 += 64){
        #pragma unroll
        for (int j = 0; j < 32; j++){
            int e = j*256 + tid; int p = e & 127; int ci = e >> 7;
            sm[p*65 + ci] = dn[(((size_t)(b*CIN + cc0 + ci)*NSTK + s)*NPNT) + p];
        }
        __syncthreads();
        #pragma unroll
        for (int j = 0; j < 32; j++){
            int e = j*256 + tid; int ci = e & 63; int p = e >> 6;
            g_xT[(rowbase + p)*CU + cc0 + ci] = sm[p*65 + ci];
        }
        __syncthreads();
    }
    if (tid < CIN) sps[tid] = sp[(b*CIN + tid)*NSTK + s];
    __syncthreads();
    #pragma unroll
    for (int j = 0; j < 64; j++){
        int e = j*256 + tid; int c = e & 127; int p = e >> 7;
        g_xT[(rowbase + p)*CU + CIN + c] = sps[c];
    }
}

// ---------------- 4) squared norms ----------------------------------------
__global__ void k_xx(){
    int w = (blockIdx.x * blockDim.x + threadIdx.x) >> 5;
    int lane = threadIdx.x & 31;
    const float* r = g_xT + (size_t)w*CU;
    float s = 0.f;
    #pragma unroll
    for (int j = 0; j < CU; j += 32){ float v = r[j+lane]; s += v*v; }
    #pragma unroll
    for (int off=16; off; off>>=1) s += __shfl_down_sync(0xffffffffu, s, off);
    if (lane == 0) g_xx[w] = s;
}

// ---------------- 5) y_nb / y_ct GEMMs: [4096,256] @ W[256,256]^T ----------
__global__ void k_wgemm(const float* __restrict__ W, const float* __restrict__ bias){
    int b = blockIdx.z >> 1, var = blockIdx.z & 1;
    int m0 = blockIdx.x*64, n0 = blockIdx.y*64;
    const float* A = g_xT + (size_t)b*NDN*CU;
    float* C = (var ? g_yct : g_ynb) + (size_t)b*NDN*COUT;
    __shared__ float As[16][68], Bs[16][68];
    int tid = threadIdx.x; int tx = tid & 15, ty = tid >> 4;
    int lr = tid >> 2, ls = tid & 3;
    float acc[4][4] = {};
    for (int kt = 0; kt < CU; kt += 16){
        float4 a = *(const float4*)(A + (size_t)(m0+lr)*CU + kt + ls*4);
        As[ls*4+0][lr]=a.x; As[ls*4+1][lr]=a.y; As[ls*4+2][lr]=a.z; As[ls*4+3][lr]=a.w;
        const float* wrow = W + (n0+lr)*(2*CU) + kt + ls*4;
        float4 wv = *(const float4*)(wrow);
        if (var){
            float4 w2 = *(const float4*)(wrow + CU);
            wv = make_float4(w2.x-wv.x, w2.y-wv.y, w2.z-wv.z, w2.w-wv.w);
        }
        Bs[ls*4+0][lr]=wv.x; Bs[ls*4+1][lr]=wv.y; Bs[ls*4+2][lr]=wv.z; Bs[ls*4+3][lr]=wv.w;
        __syncthreads();
        #pragma unroll
        for (int kk = 0; kk < 16; kk++){
            float4 av = *(const float4*)&As[kk][ty*4];
            float4 bv = *(const float4*)&Bs[kk][tx*4];
            float ar[4]={av.x,av.y,av.z,av.w}, br[4]={bv.x,bv.y,bv.z,bv.w};
            #pragma unroll
            for (int i=0;i<4;i++)
                #pragma unroll
                for (int j=0;j<4;j++) acc[i][j] += ar[i]*br[j];
        }
        __syncthreads();
    }
    #pragma unroll
    for (int i=0;i<4;i++){
        #pragma unroll
        for (int j=0;j<4;j++){
            float v = acc[i][j];
            if (var) v += bias[n0 + tx*4 + j];
            C[(size_t)(m0 + ty*4 + i)*COUT + n0 + tx*4 + j] = v;
        }
    }
}

// ---------------- 6) neg_dist = 2*x.x^T - xx_q - xx_m (the big one) --------
__global__ void k_dist(){
    int b = blockIdx.z;
    int m0 = blockIdx.x*64, q0 = blockIdx.y*64;
    const float* A = g_xT + (size_t)b*NDN*CU;
    __shared__ float As[16][68], Bs[16][68];
    int tid = threadIdx.x; int tx = tid & 15, ty = tid >> 4;
    int lr = tid >> 2, ls = tid & 3;
    float acc[4][4] = {};
    for (int kt = 0; kt < CU; kt += 16){
        float4 a = *(const float4*)(A + (size_t)(q0+lr)*CU + kt + ls*4);
        As[ls*4+0][lr]=a.x; As[ls*4+1][lr]=a.y; As[ls*4+2][lr]=a.z; As[ls*4+3][lr]=a.w;
        float4 c = *(const float4*)(A + (size_t)(m0+lr)*CU + kt + ls*4);
        Bs[ls*4+0][lr]=c.x; Bs[ls*4+1][lr]=c.y; Bs[ls*4+2][lr]=c.z; Bs[ls*4+3][lr]=c.w;
        __syncthreads();
        #pragma unroll
        for (int kk = 0; kk < 16; kk++){
            float4 av = *(const float4*)&As[kk][ty*4];
            float4 bv = *(const float4*)&Bs[kk][tx*4];
            float ar[4]={av.x,av.y,av.z,av.w}, br[4]={bv.x,bv.y,bv.z,bv.w};
            #pragma unroll
            for (int i=0;i<4;i++)
                #pragma unroll
                for (int j=0;j<4;j++) acc[i][j] += ar[i]*br[j];
        }
        __syncthreads();
    }
    float xq[4], xm[4];
    #pragma unroll
    for (int i=0;i<4;i++) xq[i] = g_xx[b*NDN + q0 + ty*4 + i];
    #pragma unroll
    for (int j=0;j<4;j++) xm[j] = g_xx[b*NDN + m0 + tx*4 + j];
    #pragma unroll
    for (int i=0;i<4;i++){
        #pragma unroll
        for (int j=0;j<4;j++){
            g_dist[(size_t)(b*NDN + q0 + ty*4 + i)*NDN + m0 + tx*4 + j]
                = 2.f*acc[i][j] - xq[i] - xm[j];
        }
    }
}

// ---------------- 7) streaming top-10 per row (stable, ties -> low index) --
__global__ void k_topk(){
    int warp = threadIdx.x >> 5, lane = threadIdx.x & 31;
    int row = blockIdx.x*4 + warp;                 // 0..32767
    const float4* r4 = (const float4*)(g_dist + (size_t)row*NDN);
    float v[10]; int ix[10];
    #pragma unroll
    for (int j=0;j<10;j++){ v[j]=NEG_INF; ix[j]=0x7fffffff; }
    for (int it = 0; it < NDN/128; it++){
        float4 f = r4[it*32 + lane];
        int mb = (it*32 + lane)*4;
        float vals[4] = {f.x, f.y, f.z, f.w};
        #pragma unroll
        for (int j=0;j<4;j++){
            float val = vals[j];
            if (val > v[9]){
                v[9]=val; ix[9]=mb+j;
                #pragma unroll
                for (int t=9;t>0;t--){
                    if (v[t] > v[t-1]){
                        float tv=v[t]; v[t]=v[t-1]; v[t-1]=tv;
                        int ti=ix[t]; ix[t]=ix[t-1]; ix[t-1]=ti;
                    }
                }
            }
        }
    }
    int* out = g_idx + row*KDN;
    #pragma unroll
    for (int r = 0; r < KDN; r++){
        float cv = v[0]; int ci = ix[0];
        #pragma unroll
        for (int off=16; off; off>>=1){
            float ov = __shfl_down_sync(0xffffffffu, cv, off);
            int   oi = __shfl_down_sync(0xffffffffu, ci, off);
            if (ov > cv || (ov == cv && oi < ci)){ cv=ov; ci=oi; }
        }
        ci = __shfl_sync(0xffffffffu, ci, 0);
        if (ci == ix[0]){
            #pragma unroll
            for (int t=0;t<9;t++){ v[t]=v[t+1]; ix[t]=ix[t+1]; }
            v[9]=NEG_INF; ix[9]=0x7fffffff;
        }
        if (lane == 0) out[r] = ci;
    }
}

// ---------------- 8) gather + BN + relu + max over k -----------------------
__global__ void k_assemble(const float* __restrict__ gam, const float* __restrict__ bet){
    int n = blockIdx.x, b = blockIdx.y, o = threadIdx.x;
    __shared__ int ids[KDN];
    if (o < KDN) ids[o] = g_idx[((size_t)b*NDN + n)*KDN + o];
    __syncthreads();
    size_t base = (size_t)b*NDN;
    float ct  = g_yct[(base + n)*COUT + o];
    float go  = gam[o]*ISQ, beo = bet[o];
    float vmax = NEG_INF;
    #pragma unroll
    for (int k = 0; k < KDN; k++){
        float h = ct + g_ynb[(base + ids[k])*COUT + o];
        h = go*h + beo;
        h = fmaxf(h, 0.f);
        vmax = fmaxf(vmax, h);
    }
    g_udn[(base + n)*COUT + o] = vmax;
}

// ---------------- 9) conv (1x3, stride 2, pad 1) + BN + relu ---------------
__global__ void k_conv(const float* __restrict__ Wc, const float* __restrict__ bc,
                       const float* __restrict__ gc, const float* __restrict__ bec,
                       float* __restrict__ yout){
    int s = blockIdx.x, b = blockIdx.y, o = threadIdx.x;
    __shared__ float sm[64][133];   // [i-chunk][p+1], rows 0 & 129 zero padding
    float acc[64];
    #pragma unroll
    for (int q=0;q<64;q++) acc[q]=0.f;
    size_t nbase = (size_t)b*NDN + (size_t)s*NPNT;
    for (int ic = 0; ic < 4; ic++){
        #pragma unroll
        for (int j = 0; j < 32; j++){
            int e = j*256 + o; int i = e & 63; int p = e >> 6;
            sm[i][p+1] = g_udn[(nbase + p)*COUT + ic*64 + i];
        }
        if (o < 64){ sm[o][0]=0.f; sm[o][129]=0.f; }
        __syncthreads();
        const float* wr = Wc + o*(COUT*3) + ic*64*3;
        for (int i = 0; i < 64; i++){
            float w0=wr[i*3], w1=wr[i*3+1], w2=wr[i*3+2];
            float xa = sm[i][0];
            #pragma unroll
            for (int q=0;q<64;q++){
                float xb = sm[i][2*q+1];
                float xc = sm[i][2*q+2];
                acc[q] += w0*xa;
                acc[q] += w1*xb;
                acc[q] += w2*xc;
                xa = xc;
            }
        }
        __syncthreads();
    }
    float bo=bc[o], go=gc[o]*ISQ, beo=bec[o];
    float* yo = yout + (((size_t)b*COUT + o)*NSTK + s)*64;
    #pragma unroll
    for (int q=0;q<64;q++){
        float v = go*(acc[q]+bo) + beo;
        yo[q] = fmaxf(v, 0.f);
    }
}

// ---------------- launch ----------------------------------------------------
extern "C" void kernel_launch(void* const* d_in, const int* in_sizes, int n_in,
                              void* d_out, int out_size){
    const float* sp    = (const float*)d_in[0];
    const float* dn    = (const float*)d_in[1];
    const float* W_sp  = (const float*)d_in[2];
    const float* b_sp  = (const float*)d_in[3];
    const float* gsp   = (const float*)d_in[4];
    const float* besp  = (const float*)d_in[5];
    const float* W_dn  = (const float*)d_in[6];
    const float* b_dn  = (const float*)d_in[7];
    const float* gdn   = (const float*)d_in[8];
    const float* bedn  = (const float*)d_in[9];
    const float* W_c   = (const float*)d_in[10];
    const float* b_c   = (const float*)d_in[11];
    const float* g_c   = (const float*)d_in[12];
    const float* be_c  = (const float*)d_in[13];
    float* out = (float*)d_out;

    k_build_sp_in<<<256, 256>>>(sp, dn);
    k_sparse_gcn <<<dim3(8,8), 256>>>(W_sp, b_sp, gsp, besp, out);
    k_build_xT   <<<dim3(NSTK, BS), 256>>>(sp, dn);
    k_xx         <<<4096, 256>>>();
    k_wgemm      <<<dim3(64, 4, 16), 256>>>(W_dn, b_dn);
    k_dist       <<<dim3(64, 64, 8), 256>>>();
    k_topk       <<<8192, 128>>>();
    k_assemble   <<<dim3(NDN, BS), 256>>>(gdn, bedn);
    k_conv       <<<dim3(NSTK, BS), 256>>>(W_c, b_c, g_c, be_c, out + BS*COUT*NSTK);
}